// round 16
// baseline (speedup 1.0000x reference)
#include <cuda_runtime.h>
#include <cuda_fp16.h>
#include <math.h>
#include <stdint.h>

// Problem constants
#define Bb_ 2
#define Tt_ 2048
#define Cc_ 2048
#define Hh_ 16
#define HKV_ 4
#define HDv_ 128
#define Mm_ (Bb_ * Tt_)
#define KVN_ 1024

// Scratch (device globals; no allocation allowed)
__device__ __half g_qh[(size_t)Mm_ * Cc_];
__device__ __half g_kvh[(size_t)Mm_ * KVN_];
__device__ __half g_yh[(size_t)Mm_ * Cc_];
__device__ __half g_xh[(size_t)Mm_ * Cc_];
__device__ __half g_wqh[(size_t)Cc_ * Cc_];
__device__ __half g_wkvh[(size_t)Cc_ * KVN_];
__device__ __half g_wph[(size_t)Cc_ * Cc_];

// ---- helpers ----------------------------------------------------------------
typedef unsigned long long u64t;

__device__ __forceinline__ u64t pk2(float lo, float hi) {
    u64t r;
    asm("mov.b64 %0, {%1, %2};" : "=l"(r) : "f"(lo), "f"(hi));
    return r;
}
__device__ __forceinline__ void mul2(u64t& d, u64t a, u64t b) {
    asm("mul.rn.f32x2 %0, %1, %2;" : "=l"(d) : "l"(a), "l"(b));
}
__device__ __forceinline__ float2 upk(u64t v) {
    float2 f;
    asm("mov.b64 {%0, %1}, %2;" : "=f"(f.x), "=f"(f.y) : "l"(v));
    return f;
}
__device__ __forceinline__ uint32_t f2h2(float a, float b) {
    const __half2 h = __floats2half2_rn(a, b);
    return *(const uint32_t*)&h;
}
__device__ __forceinline__ void mma_f16(float (&d)[4],
                                        const uint32_t (&a)[4],
                                        const uint32_t (&b)[2]) {
    asm volatile(
        "mma.sync.aligned.m16n8k16.row.col.f32.f16.f16.f32 "
        "{%0,%1,%2,%3}, {%4,%5,%6,%7}, {%8,%9}, {%0,%1,%2,%3};\n"
        : "+f"(d[0]), "+f"(d[1]), "+f"(d[2]), "+f"(d[3])
        : "r"(a[0]), "r"(a[1]), "r"(a[2]), "r"(a[3]), "r"(b[0]), "r"(b[1]));
}
__device__ __forceinline__ void ldsm_x4(uint32_t (&r)[4], uint32_t addr) {
    asm volatile(
        "ldmatrix.sync.aligned.m8n8.x4.shared.b16 {%0,%1,%2,%3}, [%4];"
        : "=r"(r[0]), "=r"(r[1]), "=r"(r[2]), "=r"(r[3]) : "r"(addr));
}
__device__ __forceinline__ void ldsm_x4t(uint32_t (&r)[4], uint32_t addr) {
    asm volatile(
        "ldmatrix.sync.aligned.m8n8.x4.trans.shared.b16 {%0,%1,%2,%3}, [%4];"
        : "=r"(r[0]), "=r"(r[1]), "=r"(r[2]), "=r"(r[3]) : "r"(addr));
}
__device__ __forceinline__ uint32_t smem_u32(const void* p) {
    uint32_t a;
    asm("{ .reg .u64 t; cvta.to.shared.u64 t, %1; cvt.u32.u64 %0, t; }"
        : "=r"(a) : "l"(p));
    return a;
}
__device__ __forceinline__ void cp16(uint32_t dst, const void* src) {
    asm volatile("cp.async.cg.shared.global [%0], [%1], 16;"
                 :: "r"(dst), "l"(src));
}
#define CP_COMMIT() asm volatile("cp.async.commit_group;" ::: "memory")
#define CP_WAIT(n)  asm volatile("cp.async.wait_group %0;" :: "n"(n) : "memory")

// ---------------------------------------------------------------------------
// One fused fp32 -> fp16 conversion over all four inputs.
// ---------------------------------------------------------------------------
__global__ void __launch_bounds__(256)
conv_all(const float* __restrict__ x,   __half* __restrict__ xh,
         const float* __restrict__ wq,  __half* __restrict__ wqh,
         const float* __restrict__ wkv, __half* __restrict__ wkvh,
         const float* __restrict__ wp,  __half* __restrict__ wph)
{
    const int blk = blockIdx.x;
    const float* in;
    __half* out;
    int rel;
    if (blk < 8192)        { in = x;   out = xh;   rel = blk; }
    else if (blk < 12288)  { in = wq;  out = wqh;  rel = blk - 8192; }
    else if (blk < 14336)  { in = wkv; out = wkvh; rel = blk - 12288; }
    else                   { in = wp;  out = wph;  rel = blk - 14336; }

    const size_t i = ((size_t)rel * 256 + threadIdx.x) * 4;
    const float4 v = *(const float4*)(in + i);
    *(__half2*)(out + i)     = __floats2half2_rn(v.x, v.y);
    *(__half2*)(out + i + 2) = __floats2half2_rn(v.z, v.w);
}

// ---------------------------------------------------------------------------
// fp16 m16n8k16 GEMM core, BK=64, 3-stage cp.async, wide-ldmatrix fragments.
// 128x128 CTA, 8 warps (64x32).
// ---------------------------------------------------------------------------
#define GSTG 3
#define LDAH 72
#define LDBH 136
#define A_BYTES (128 * LDAH * 2)
#define B_BYTES (64 * LDBH * 2)
#define STG_BYTES (A_BYTES + B_BYTES)
#define GEMM_SMEM (GSTG * STG_BYTES)

__device__ __forceinline__ void gemm_issue_h(uint32_t sb, int buf,
                                             const __half* Ah, const __half* Bh,
                                             int K, int N, int k0, int tid)
{
    const uint32_t base = sb + buf * STG_BYTES;
#pragma unroll
    for (int u = 0; u < 4; u++) {
        const int ia = tid + u * 256;
        const int m  = ia >> 3;
        const int c8 = (ia & 7) * 8;
        cp16(base + (m * LDAH + c8) * 2, Ah + (size_t)m * K + k0 + c8);
        const int ib = tid + u * 256;
        const int k  = ib >> 4;
        const int n8 = (ib & 15) * 8;
        cp16(base + A_BYTES + (k * LDBH + n8) * 2,
             Bh + (size_t)(k0 + k) * N + n8);
    }
}

// outMode: 0 -> fp32 C, 1 -> fp16 C (scaled by outScale)
template <int outMode>
__device__ __forceinline__ void gemm_core_h(const __half* Ah, const __half* Bh,
                                            const float* biasb, void* Cb,
                                            int K, int N, float outScale,
                                            uint32_t sb)
{
    const int tid  = threadIdx.x;
    const int wid  = tid >> 5;
    const int lane = tid & 31;
    const int g    = lane >> 2;
    const int tg   = lane & 3;
    const int wm   = wid & 1;
    const int wn   = wid >> 1;

    const int arow_l = (lane & 7) + 8 * ((lane >> 3) & 1);
    const int acol_l = (lane >> 4) * 8;
    // x4t B lane mapping: matrices (k lo/hi) x (n, n+8)
    const int bkrow_l = (lane & 7) + 8 * ((lane >> 3) & 1);
    const int bcol_l  = (lane >> 4) * 8;   // 0 or 8 within 16-col pair

    float acc[4][4][4];
#pragma unroll
    for (int mi = 0; mi < 4; mi++)
#pragma unroll
        for (int ni = 0; ni < 4; ni++)
#pragma unroll
            for (int r = 0; r < 4; r++) acc[mi][ni][r] = 0.f;

    const int nt = K / 64;

#pragma unroll
    for (int s = 0; s < GSTG - 1; s++) {
        if (s < nt) gemm_issue_h(sb, s, Ah, Bh, K, N, s * 64, tid);
        CP_COMMIT();
    }

    int buf = 0;
    for (int t = 0; t < nt; ++t) {
        CP_WAIT(1);
        __syncthreads();
        if (t + 2 < nt)
            gemm_issue_h(sb, (t + 2) % GSTG, Ah, Bh, K, N, (t + 2) * 64, tid);
        CP_COMMIT();

        const uint32_t base = sb + buf * STG_BYTES;
#pragma unroll
        for (int kc = 0; kc < 4; kc++) {
            uint32_t afr[4][4];
#pragma unroll
            for (int mi = 0; mi < 4; mi++) {
                const int row = wm * 64 + mi * 16 + arow_l;
                const int col = kc * 16 + acol_l;
                ldsm_x4(afr[mi], base + (row * LDAH + col) * 2);
            }
            uint32_t bfr[4][2];
#pragma unroll
            for (int nip = 0; nip < 2; nip++) {  // pairs (0,1) (2,3)
                uint32_t bb[4];
                const int krow = kc * 16 + bkrow_l;
                const int ncol = wn * 32 + nip * 16 + bcol_l;
                ldsm_x4t(bb, base + A_BYTES + (krow * LDBH + ncol) * 2);
                bfr[2 * nip][0] = bb[0];  bfr[2 * nip][1] = bb[1];
                bfr[2 * nip + 1][0] = bb[2]; bfr[2 * nip + 1][1] = bb[3];
            }
#pragma unroll
            for (int mi = 0; mi < 4; mi++)
#pragma unroll
                for (int ni = 0; ni < 4; ni++)
                    mma_f16(acc[mi][ni], afr[mi], bfr[ni]);
        }
        buf = (buf + 1 == GSTG) ? 0 : buf + 1;
    }

    // ---- epilogue: fused bias (+ scale for fp16 outputs) ----
#pragma unroll
    for (int mi = 0; mi < 4; mi++) {
        const int r0 = wm * 64 + mi * 16 + g;
#pragma unroll
        for (int ni = 0; ni < 4; ni++) {
            const int c0 = wn * 32 + ni * 8 + tg * 2;
            const float bx0 = biasb[c0], bx1 = biasb[c0 + 1];
            const float a0 = acc[mi][ni][0] + bx0;
            const float a1 = acc[mi][ni][1] + bx1;
            const float a2 = acc[mi][ni][2] + bx0;
            const float a3 = acc[mi][ni][3] + bx1;
            if (outMode == 0) {
                float* Cf = (float*)Cb;
                *(float2*)(Cf + (size_t)r0 * N + c0)       = make_float2(a0, a1);
                *(float2*)(Cf + (size_t)(r0 + 8) * N + c0) = make_float2(a2, a3);
            } else {
                __half* Ch = (__half*)Cb;
                *(__half2*)(Ch + (size_t)r0 * N + c0) =
                    __floats2half2_rn(a0 * outScale, a1 * outScale);
                *(__half2*)(Ch + (size_t)(r0 + 8) * N + c0) =
                    __floats2half2_rn(a2 * outScale, a3 * outScale);
            }
        }
    }
}

// Fused q+kv projection (fp16 outputs). q pre-scaled by 1/sqrt(HD).
__global__ void __launch_bounds__(256, 2)
qkv_gemm(const __half* __restrict__ xh,
         const __half* __restrict__ wqh, const float* __restrict__ bq,
         const __half* __restrict__ wkvh, const float* __restrict__ bkv,
         __half* __restrict__ qh, __half* __restrict__ kvh)
{
    extern __shared__ uint32_t smw[];
    const uint32_t sb = smem_u32(smw);
    const int bx = blockIdx.x;
    const __half* Ab = xh + (size_t)blockIdx.y * 128 * Cc_;

    if (bx < 16) {
        const int cb = bx * 128;
        gemm_core_h<1>(Ab, wqh + cb, bq + cb,
                       qh + (size_t)blockIdx.y * 128 * Cc_ + cb,
                       Cc_, Cc_, 0.08838834764831843f, sb);
    } else {
        const int cb = (bx - 16) * 128;
        gemm_core_h<1>(Ab, wkvh + cb, bkv + cb,
                       kvh + (size_t)blockIdx.y * 128 * KVN_ + cb,
                       Cc_, KVN_, 1.0f, sb);
    }
}

// Final projection: out = yh @ Wp + bp (fp32 output)
__global__ void __launch_bounds__(256, 2)
pgemm_h(const __half* __restrict__ A, const __half* __restrict__ B,
        const float* __restrict__ bias, float* __restrict__ C)
{
    extern __shared__ uint32_t smw[];
    const uint32_t sb = smem_u32(smw);
    const int cb = blockIdx.x * 128;
    gemm_core_h<0>(A + (size_t)blockIdx.y * 128 * Cc_, B + cb, bias + cb,
                   C + (size_t)blockIdx.y * 128 * Cc_ + cb,
                   Cc_, Cc_, 1.0f, sb);
}

// ---------------------------------------------------------------------------
// Flash attention, fp16 m16n8k16, Bc=128, double-buffered cp.async K/V,
// register-resident P, wide-ldmatrix K/V fragments, diagonal MMA skipping.
// ---------------------------------------------------------------------------
#define LDKH 136
#define KVB (128 * LDKH * 2)
#define STG_FB (2 * KVB)
#define FLASH_SMEM (2 * STG_FB)

__device__ __forceinline__ void flash_issue_h(uint32_t sb, int buf,
                                              const __half* kvbase, int tid)
{
    const uint32_t kb = sb + buf * STG_FB;
    const uint32_t vb = kb + KVB;
#pragma unroll
    for (int u = 0; u < 8; u++) {
        const int i  = tid + u * 256;
        const int r  = i >> 4;
        const int c8 = (i & 15) * 8;
        const __half* src = kvbase + (size_t)r * KVN_ + c8;
        cp16(kb + (r * LDKH + c8) * 2, src);
        cp16(vb + (r * LDKH + c8) * 2, src + 512);
    }
}

__global__ void __launch_bounds__(256, 1)
flash_h(const __half* __restrict__ q, const __half* __restrict__ kv,
        __half* __restrict__ y)
{
    extern __shared__ char smc[];
    const uint32_t sb = smem_u32(smc);

    const int qt = (int)gridDim.x - 1 - (int)blockIdx.x;  // longest-first
    const int h  = blockIdx.y;
    const int b  = blockIdx.z;
    const int kvh = h & (HKV_ - 1);

    const int tid  = threadIdx.x;
    const int w    = tid >> 5;
    const int lane = tid & 31;
    const int g    = lane >> 2;
    const int tg   = lane & 3;

    // S-loop ldsm_x4 (non-trans) lane mapping:
    //   mats: (n-lo klo), (n-lo khi), (n-hi klo), (n-hi khi)
    const int s_nrow = ((lane >> 4) & 1) * 8 + (lane & 7);  // row in 16-n block
    const int s_koff = ((lane >> 3) & 1) * 8;               // 0/8 within 16-k
    // V-loop ldsm_x4t lane mapping: (k rows lo/hi) x (n, n+8)
    const int v_krow = ((lane >> 3) & 1) * 8 + (lane & 7);
    const int v_csel = (lane >> 4);                         // 0/1 -> col +0/+8

    const int rloc0 = w * 16 + g;
    const int grow0 = qt * 128 + rloc0;
    const int grow1 = grow0 + 8;

    // ---- load Q once as fp16 A-fragments (pre-scaled by qkv_gemm) ----
    uint32_t qf[8][4];
    {
        const __half* qb = q + ((size_t)(b * Tt_) + qt * 128 + w * 16) * Cc_
                             + h * HDv_;
#pragma unroll
        for (int kc = 0; kc < 8; kc++) {
            const int d0 = kc * 16 + tg * 2;
            qf[kc][0] = *(const uint32_t*)(qb + (size_t)g * Cc_ + d0);
            qf[kc][1] = *(const uint32_t*)(qb + (size_t)(g + 8) * Cc_ + d0);
            qf[kc][2] = *(const uint32_t*)(qb + (size_t)g * Cc_ + d0 + 8);
            qf[kc][3] = *(const uint32_t*)(qb + (size_t)(g + 8) * Cc_ + d0 + 8);
        }
    }

    float of[16][4];
#pragma unroll
    for (int ni = 0; ni < 16; ni++)
#pragma unroll
        for (int r = 0; r < 4; r++) of[ni][r] = 0.f;
    float m0 = -INFINITY, m1 = -INFINITY, l0 = 0.f, l1 = 0.f;

    const __half* kvb0 = kv + (size_t)(b * Tt_) * KVN_ + kvh * HDv_;

    flash_issue_h(sb, 0, kvb0, tid);
    CP_COMMIT();

    for (int kt = 0; kt <= qt; ++kt) {
        const int cur = kt & 1;
        CP_WAIT(0);
        __syncthreads();
        if (kt < qt) {
            flash_issue_h(sb, cur ^ 1, kvb0 + (size_t)(kt + 1) * 128 * KVN_, tid);
            CP_COMMIT();
        }

        const uint32_t kbase = sb + cur * STG_FB;
        const uint32_t vbase = kbase + KVB;

        const bool diag = (kt == qt);
        const int nipmax = diag ? (w + 1) : 8;   // active S n-tile PAIRS
        const int kcmax  = diag ? (w + 1) : 8;   // active PV k-chunks

        // ---- S = Q K^T : ldsm_x4 feeds two n-tiles per instruction ----
        float sf[16][4];
#pragma unroll
        for (int ni = 0; ni < 16; ni++)
#pragma unroll
            for (int r = 0; r < 4; r++) sf[ni][r] = 0.f;

#pragma unroll
        for (int kc = 0; kc < 8; kc++) {
#pragma unroll
            for (int nip = 0; nip < 8; nip++) {
                if (nip < nipmax) {
                    uint32_t bb[4];
                    ldsm_x4(bb, kbase +
                            ((nip * 16 + s_nrow) * LDKH + kc * 16 + s_koff) * 2);
                    const uint32_t b0[2] = {bb[0], bb[1]};
                    const uint32_t b1[2] = {bb[2], bb[3]};
                    mma_f16(sf[2 * nip], qf[kc], b0);
                    mma_f16(sf[2 * nip + 1], qf[kc], b1);
                }
            }
        }

        // ---- causal mask (diagonal tile only) ----
        if (diag) {
#pragma unroll
            for (int ni = 0; ni < 16; ni++) {
                if (ni >= 2 * nipmax) {
                    sf[ni][0] = sf[ni][1] = sf[ni][2] = sf[ni][3] = -1e30f;
                } else {
                    const int c0 = kt * 128 + ni * 8 + tg * 2;
                    if (c0 > grow0)     sf[ni][0] = -1e30f;
                    if (c0 + 1 > grow0) sf[ni][1] = -1e30f;
                    if (c0 > grow1)     sf[ni][2] = -1e30f;
                    if (c0 + 1 > grow1) sf[ni][3] = -1e30f;
                }
            }
        }

        // ---- online softmax (rows g, g+8) ----
        float mx0 = -1e30f, mx1 = -1e30f;
#pragma unroll
        for (int ni = 0; ni < 16; ni++) {
            mx0 = fmaxf(mx0, fmaxf(sf[ni][0], sf[ni][1]));
            mx1 = fmaxf(mx1, fmaxf(sf[ni][2], sf[ni][3]));
        }
        mx0 = fmaxf(mx0, __shfl_xor_sync(0xffffffffu, mx0, 1));
        mx0 = fmaxf(mx0, __shfl_xor_sync(0xffffffffu, mx0, 2));
        mx1 = fmaxf(mx1, __shfl_xor_sync(0xffffffffu, mx1, 1));
        mx1 = fmaxf(mx1, __shfl_xor_sync(0xffffffffu, mx1, 2));

        const float nm0 = fmaxf(m0, mx0);
        const float nm1 = fmaxf(m1, mx1);
        float sum0 = 0.f, sum1 = 0.f;
#pragma unroll
        for (int ni = 0; ni < 16; ni++) {
            sf[ni][0] = __expf(sf[ni][0] - nm0);
            sf[ni][1] = __expf(sf[ni][1] - nm0);
            sf[ni][2] = __expf(sf[ni][2] - nm1);
            sf[ni][3] = __expf(sf[ni][3] - nm1);
            sum0 += sf[ni][0] + sf[ni][1];
            sum1 += sf[ni][2] + sf[ni][3];
        }
        sum0 += __shfl_xor_sync(0xffffffffu, sum0, 1);
        sum0 += __shfl_xor_sync(0xffffffffu, sum0, 2);
        sum1 += __shfl_xor_sync(0xffffffffu, sum1, 1);
        sum1 += __shfl_xor_sync(0xffffffffu, sum1, 2);

        const float al0 = __expf(m0 - nm0);
        const float al1 = __expf(m1 - nm1);
        m0 = nm0; m1 = nm1;
        l0 = l0 * al0 + sum0;
        l1 = l1 * al1 + sum1;

        // ---- rescale O ----
        {
            const u64t a0p = pk2(al0, al0);
            const u64t a1p = pk2(al1, al1);
#pragma unroll
            for (int ni = 0; ni < 16; ni++) {
                u64t v01 = pk2(of[ni][0], of[ni][1]);
                u64t v23 = pk2(of[ni][2], of[ni][3]);
                mul2(v01, v01, a0p);
                mul2(v23, v23, a1p);
                const float2 f01 = upk(v01), f23 = upk(v23);
                of[ni][0] = f01.x; of[ni][1] = f01.y;
                of[ni][2] = f23.x; of[ni][3] = f23.y;
            }
        }

        // ---- O += P V : register P, ldsm_x4t feeds two n-tiles ----
#pragma unroll
        for (int kc = 0; kc < 8; kc++) {
            if (kc < kcmax) {
                uint32_t pa[4];
                pa[0] = f2h2(sf[2 * kc][0],     sf[2 * kc][1]);
                pa[1] = f2h2(sf[2 * kc][2],     sf[2 * kc][3]);
                pa[2] = f2h2(sf[2 * kc + 1][0], sf[2 * kc + 1][1]);
                pa[3] = f2h2(sf[2 * kc + 1][2], sf[2 * kc + 1][3]);
#pragma unroll
                for (int nip = 0; nip < 8; nip++) {
                    uint32_t vv[4];
                    ldsm_x4t(vv, vbase +
                             ((kc * 16 + v_krow) * LDKH +
                              (nip * 2 + v_csel) * 8) * 2);
                    const uint32_t v0[2] = {vv[0], vv[1]};
                    const uint32_t v1[2] = {vv[2], vv[3]};
                    mma_f16(of[2 * nip], pa, v0);
                    mma_f16(of[2 * nip + 1], pa, v1);
                }
            }
        }
    }

    // ---- normalize + store fp16 ----
    const float inv0 = 1.f / l0;
    const float inv1 = 1.f / l1;
    __half* y0 = y + ((size_t)(b * Tt_) + grow0) * Cc_ + h * HDv_;
    __half* y1 = y + ((size_t)(b * Tt_) + grow1) * Cc_ + h * HDv_;
#pragma unroll
    for (int ni = 0; ni < 16; ni++) {
        const int c0 = ni * 8 + tg * 2;
        *(__half2*)(y0 + c0) =
            __floats2half2_rn(of[ni][0] * inv0, of[ni][1] * inv0);
        *(__half2*)(y1 + c0) =
            __floats2half2_rn(of[ni][2] * inv1, of[ni][3] * inv1);
    }
}

// ---------------------------------------------------------------------------
extern "C" void kernel_launch(void* const* d_in, const int* in_sizes, int n_in,
                              void* d_out, int out_size)
{
    const float* x   = (const float*)d_in[0];
    const float* Wkv = (const float*)d_in[1];
    const float* bkv = (const float*)d_in[2];
    const float* Wq  = (const float*)d_in[3];
    const float* bq  = (const float*)d_in[4];
    const float* Wp  = (const float*)d_in[5];
    const float* bp  = (const float*)d_in[6];
    float* out = (float*)d_out;

    __half *qh, *kvh, *yh, *xh, *wqh, *wkvh, *wph;
    cudaGetSymbolAddress((void**)&qh,   g_qh);
    cudaGetSymbolAddress((void**)&kvh,  g_kvh);
    cudaGetSymbolAddress((void**)&yh,   g_yh);
    cudaGetSymbolAddress((void**)&xh,   g_xh);
    cudaGetSymbolAddress((void**)&wqh,  g_wqh);
    cudaGetSymbolAddress((void**)&wkvh, g_wkvh);
    cudaGetSymbolAddress((void**)&wph,  g_wph);

    cudaFuncSetAttribute(qkv_gemm,
                         cudaFuncAttributeMaxDynamicSharedMemorySize,
                         GEMM_SMEM);
    cudaFuncSetAttribute(pgemm_h,
                         cudaFuncAttributeMaxDynamicSharedMemorySize,
                         GEMM_SMEM);
    cudaFuncSetAttribute(flash_h,
                         cudaFuncAttributeMaxDynamicSharedMemorySize,
                         FLASH_SMEM);

    // one fused fp16 conversion of all GEMM inputs
    conv_all<<<18432, 256>>>(x, xh, Wq, wqh, Wkv, wkvh, Wp, wph);

    // fused q + kv projections (q pre-scaled by 1/sqrt(HD))
    qkv_gemm<<<dim3(24, Mm_ / 128), 256, GEMM_SMEM>>>(
        xh, wqh, bq, wkvh, bkv, qh, kvh);
    // attention
    flash_h<<<dim3(Tt_ / 128, Hh_, Bb_), 256, FLASH_SMEM>>>(qh, kvh, yh);
    // out = y @ Wp + bp
    pgemm_h<<<dim3(Cc_ / 128, Mm_ / 128), 256, GEMM_SMEM>>>(yh, wph, bp, out);
}

// round 17
// speedup vs baseline: 1.0752x; 1.0752x over previous
#include <cuda_runtime.h>
#include <cuda_fp16.h>
#include <math.h>
#include <stdint.h>

// Problem constants
#define Bb_ 2
#define Tt_ 2048
#define Cc_ 2048
#define Hh_ 16
#define HKV_ 4
#define HDv_ 128
#define Mm_ (Bb_ * Tt_)
#define KVN_ 1024

// Scratch (device globals; no allocation allowed)
__device__ __half g_qh[(size_t)Mm_ * Cc_];
__device__ __half g_kvh[(size_t)Mm_ * KVN_];
__device__ __half g_yh[(size_t)Mm_ * Cc_];
__device__ __half g_xh[(size_t)Mm_ * Cc_];
__device__ __half g_wqh[(size_t)Cc_ * Cc_];
__device__ __half g_wkvh[(size_t)Cc_ * KVN_];
__device__ __half g_wph[(size_t)Cc_ * Cc_];

// ---- helpers ----------------------------------------------------------------
typedef unsigned long long u64t;

__device__ __forceinline__ u64t pk2(float lo, float hi) {
    u64t r;
    asm("mov.b64 %0, {%1, %2};" : "=l"(r) : "f"(lo), "f"(hi));
    return r;
}
__device__ __forceinline__ void mul2(u64t& d, u64t a, u64t b) {
    asm("mul.rn.f32x2 %0, %1, %2;" : "=l"(d) : "l"(a), "l"(b));
}
__device__ __forceinline__ float2 upk(u64t v) {
    float2 f;
    asm("mov.b64 {%0, %1}, %2;" : "=f"(f.x), "=f"(f.y) : "l"(v));
    return f;
}
__device__ __forceinline__ uint32_t f2h2(float a, float b) {
    const __half2 h = __floats2half2_rn(a, b);
    return *(const uint32_t*)&h;
}
__device__ __forceinline__ void mma_f16(float (&d)[4],
                                        const uint32_t (&a)[4],
                                        const uint32_t (&b)[2]) {
    asm volatile(
        "mma.sync.aligned.m16n8k16.row.col.f32.f16.f16.f32 "
        "{%0,%1,%2,%3}, {%4,%5,%6,%7}, {%8,%9}, {%0,%1,%2,%3};\n"
        : "+f"(d[0]), "+f"(d[1]), "+f"(d[2]), "+f"(d[3])
        : "r"(a[0]), "r"(a[1]), "r"(a[2]), "r"(a[3]), "r"(b[0]), "r"(b[1]));
}
__device__ __forceinline__ void ldsm_x4(uint32_t (&r)[4], uint32_t addr) {
    asm volatile(
        "ldmatrix.sync.aligned.m8n8.x4.shared.b16 {%0,%1,%2,%3}, [%4];"
        : "=r"(r[0]), "=r"(r[1]), "=r"(r[2]), "=r"(r[3]) : "r"(addr));
}
__device__ __forceinline__ void ldsm_x4t(uint32_t (&r)[4], uint32_t addr) {
    asm volatile(
        "ldmatrix.sync.aligned.m8n8.x4.trans.shared.b16 {%0,%1,%2,%3}, [%4];"
        : "=r"(r[0]), "=r"(r[1]), "=r"(r[2]), "=r"(r[3]) : "r"(addr));
}
__device__ __forceinline__ void ldsm_x2t(uint32_t (&r)[2], uint32_t addr) {
    asm volatile(
        "ldmatrix.sync.aligned.m8n8.x2.trans.shared.b16 {%0,%1}, [%2];"
        : "=r"(r[0]), "=r"(r[1]) : "r"(addr));
}
__device__ __forceinline__ uint32_t smem_u32(const void* p) {
    uint32_t a;
    asm("{ .reg .u64 t; cvta.to.shared.u64 t, %1; cvt.u32.u64 %0, t; }"
        : "=r"(a) : "l"(p));
    return a;
}
__device__ __forceinline__ void cp16(uint32_t dst, const void* src) {
    asm volatile("cp.async.cg.shared.global [%0], [%1], 16;"
                 :: "r"(dst), "l"(src));
}
#define CP_COMMIT() asm volatile("cp.async.commit_group;" ::: "memory")
#define CP_WAIT(n)  asm volatile("cp.async.wait_group %0;" :: "n"(n) : "memory")

// ---------------------------------------------------------------------------
// One fused fp32 -> fp16 conversion over all four inputs.
// ---------------------------------------------------------------------------
__global__ void __launch_bounds__(256)
conv_all(const float* __restrict__ x,   __half* __restrict__ xh,
         const float* __restrict__ wq,  __half* __restrict__ wqh,
         const float* __restrict__ wkv, __half* __restrict__ wkvh,
         const float* __restrict__ wp,  __half* __restrict__ wph)
{
    const int blk = blockIdx.x;
    const float* in;
    __half* out;
    int rel;
    if (blk < 8192)        { in = x;   out = xh;   rel = blk; }
    else if (blk < 12288)  { in = wq;  out = wqh;  rel = blk - 8192; }
    else if (blk < 14336)  { in = wkv; out = wkvh; rel = blk - 12288; }
    else                   { in = wp;  out = wph;  rel = blk - 14336; }

    const size_t i = ((size_t)rel * 256 + threadIdx.x) * 4;
    const float4 v = *(const float4*)(in + i);
    *(__half2*)(out + i)     = __floats2half2_rn(v.x, v.y);
    *(__half2*)(out + i + 2) = __floats2half2_rn(v.z, v.w);
}

// ---------------------------------------------------------------------------
// fp16 m16n8k16 GEMM core, BK=64, 3-stage cp.async, ldmatrix fragments
// (A: x4, B: paired x4t). 128x128 CTA, 8 warps (64x32).
// ---------------------------------------------------------------------------
#define GSTG 3
#define LDAH 72
#define LDBH 136
#define A_BYTES (128 * LDAH * 2)
#define B_BYTES (64 * LDBH * 2)
#define STG_BYTES (A_BYTES + B_BYTES)
#define GEMM_SMEM (GSTG * STG_BYTES)

__device__ __forceinline__ void gemm_issue_h(uint32_t sb, int buf,
                                             const __half* Ah, const __half* Bh,
                                             int K, int N, int k0, int tid)
{
    const uint32_t base = sb + buf * STG_BYTES;
#pragma unroll
    for (int u = 0; u < 4; u++) {
        const int ia = tid + u * 256;
        const int m  = ia >> 3;
        const int c8 = (ia & 7) * 8;
        cp16(base + (m * LDAH + c8) * 2, Ah + (size_t)m * K + k0 + c8);
        const int ib = tid + u * 256;
        const int k  = ib >> 4;
        const int n8 = (ib & 15) * 8;
        cp16(base + A_BYTES + (k * LDBH + n8) * 2,
             Bh + (size_t)(k0 + k) * N + n8);
    }
}

// outMode: 0 -> fp32 C, 1 -> fp16 C (scaled by outScale)
template <int outMode>
__device__ __forceinline__ void gemm_core_h(const __half* Ah, const __half* Bh,
                                            const float* biasb, void* Cb,
                                            int K, int N, float outScale,
                                            uint32_t sb)
{
    const int tid  = threadIdx.x;
    const int wid  = tid >> 5;
    const int lane = tid & 31;
    const int g    = lane >> 2;
    const int tg   = lane & 3;
    const int wm   = wid & 1;
    const int wn   = wid >> 1;

    const int arow_l = (lane & 7) + 8 * ((lane >> 3) & 1);
    const int acol_l = (lane >> 4) * 8;
    // x4t B lane mapping: matrices (k lo/hi) x (n, n+8)
    const int bkrow_l = (lane & 7) + 8 * ((lane >> 3) & 1);
    const int bcol_l  = (lane >> 4) * 8;

    float acc[4][4][4];
#pragma unroll
    for (int mi = 0; mi < 4; mi++)
#pragma unroll
        for (int ni = 0; ni < 4; ni++)
#pragma unroll
            for (int r = 0; r < 4; r++) acc[mi][ni][r] = 0.f;

    const int nt = K / 64;

#pragma unroll
    for (int s = 0; s < GSTG - 1; s++) {
        if (s < nt) gemm_issue_h(sb, s, Ah, Bh, K, N, s * 64, tid);
        CP_COMMIT();
    }

    int buf = 0;
    for (int t = 0; t < nt; ++t) {
        CP_WAIT(1);
        __syncthreads();
        if (t + 2 < nt)
            gemm_issue_h(sb, (t + 2) % GSTG, Ah, Bh, K, N, (t + 2) * 64, tid);
        CP_COMMIT();

        const uint32_t base = sb + buf * STG_BYTES;
#pragma unroll
        for (int kc = 0; kc < 4; kc++) {
            uint32_t afr[4][4];
#pragma unroll
            for (int mi = 0; mi < 4; mi++) {
                const int row = wm * 64 + mi * 16 + arow_l;
                const int col = kc * 16 + acol_l;
                ldsm_x4(afr[mi], base + (row * LDAH + col) * 2);
            }
            uint32_t bfr[4][2];
#pragma unroll
            for (int nip = 0; nip < 2; nip++) {
                uint32_t bb[4];
                const int krow = kc * 16 + bkrow_l;
                const int ncol = wn * 32 + nip * 16 + bcol_l;
                ldsm_x4t(bb, base + A_BYTES + (krow * LDBH + ncol) * 2);
                bfr[2 * nip][0] = bb[0];  bfr[2 * nip][1] = bb[1];
                bfr[2 * nip + 1][0] = bb[2]; bfr[2 * nip + 1][1] = bb[3];
            }
#pragma unroll
            for (int mi = 0; mi < 4; mi++)
#pragma unroll
                for (int ni = 0; ni < 4; ni++)
                    mma_f16(acc[mi][ni], afr[mi], bfr[ni]);
        }
        buf = (buf + 1 == GSTG) ? 0 : buf + 1;
    }

    // ---- epilogue: fused bias (+ scale for fp16 outputs) ----
#pragma unroll
    for (int mi = 0; mi < 4; mi++) {
        const int r0 = wm * 64 + mi * 16 + g;
#pragma unroll
        for (int ni = 0; ni < 4; ni++) {
            const int c0 = wn * 32 + ni * 8 + tg * 2;
            const float bx0 = biasb[c0], bx1 = biasb[c0 + 1];
            const float a0 = acc[mi][ni][0] + bx0;
            const float a1 = acc[mi][ni][1] + bx1;
            const float a2 = acc[mi][ni][2] + bx0;
            const float a3 = acc[mi][ni][3] + bx1;
            if (outMode == 0) {
                float* Cf = (float*)Cb;
                *(float2*)(Cf + (size_t)r0 * N + c0)       = make_float2(a0, a1);
                *(float2*)(Cf + (size_t)(r0 + 8) * N + c0) = make_float2(a2, a3);
            } else {
                __half* Ch = (__half*)Cb;
                *(__half2*)(Ch + (size_t)r0 * N + c0) =
                    __floats2half2_rn(a0 * outScale, a1 * outScale);
                *(__half2*)(Ch + (size_t)(r0 + 8) * N + c0) =
                    __floats2half2_rn(a2 * outScale, a3 * outScale);
            }
        }
    }
}

// Fused q+kv projection (fp16 outputs). q pre-scaled by 1/sqrt(HD).
__global__ void __launch_bounds__(256, 2)
qkv_gemm(const __half* __restrict__ xh,
         const __half* __restrict__ wqh, const float* __restrict__ bq,
         const __half* __restrict__ wkvh, const float* __restrict__ bkv,
         __half* __restrict__ qh, __half* __restrict__ kvh)
{
    extern __shared__ uint32_t smw[];
    const uint32_t sb = smem_u32(smw);
    const int bx = blockIdx.x;
    const __half* Ab = xh + (size_t)blockIdx.y * 128 * Cc_;

    if (bx < 16) {
        const int cb = bx * 128;
        gemm_core_h<1>(Ab, wqh + cb, bq + cb,
                       qh + (size_t)blockIdx.y * 128 * Cc_ + cb,
                       Cc_, Cc_, 0.08838834764831843f, sb);
    } else {
        const int cb = (bx - 16) * 128;
        gemm_core_h<1>(Ab, wkvh + cb, bkv + cb,
                       kvh + (size_t)blockIdx.y * 128 * KVN_ + cb,
                       Cc_, KVN_, 1.0f, sb);
    }
}

// Final projection: out = yh @ Wp + bp (fp32 output)
__global__ void __launch_bounds__(256, 2)
pgemm_h(const __half* __restrict__ A, const __half* __restrict__ B,
        const float* __restrict__ bias, float* __restrict__ C)
{
    extern __shared__ uint32_t smw[];
    const uint32_t sb = smem_u32(smw);
    const int cb = blockIdx.x * 128;
    gemm_core_h<0>(A + (size_t)blockIdx.y * 128 * Cc_, B + cb, bias + cb,
                   C + (size_t)blockIdx.y * 128 * Cc_ + cb,
                   Cc_, Cc_, 1.0f, sb);
}

// ---------------------------------------------------------------------------
// Flash attention (reverted to R14-submission form, 459.8us config):
// fp16 m16n8k16, Bc=128, double-buffered cp.async K/V, one sync per kt,
// register-resident P, scalar-LDS K frags, ldsm_x2t V frags,
// diagonal-tile MMA skipping. Br=128 (8 warps x 16 rows), HD=128.
// ---------------------------------------------------------------------------
#define LDKH 136
#define KVB (128 * LDKH * 2)
#define STG_FB (2 * KVB)
#define FLASH_SMEM (2 * STG_FB)

__device__ __forceinline__ void flash_issue_h(uint32_t sb, int buf,
                                              const __half* kvbase, int tid)
{
    const uint32_t kb = sb + buf * STG_FB;
    const uint32_t vb = kb + KVB;
#pragma unroll
    for (int u = 0; u < 8; u++) {
        const int i  = tid + u * 256;
        const int r  = i >> 4;
        const int c8 = (i & 15) * 8;
        const __half* src = kvbase + (size_t)r * KVN_ + c8;
        cp16(kb + (r * LDKH + c8) * 2, src);
        cp16(vb + (r * LDKH + c8) * 2, src + 512);
    }
}

__global__ void __launch_bounds__(256, 1)
flash_h(const __half* __restrict__ q, const __half* __restrict__ kv,
        __half* __restrict__ y)
{
    extern __shared__ char smc[];
    const uint32_t sb = smem_u32(smc);

    const int qt = (int)gridDim.x - 1 - (int)blockIdx.x;  // longest-first
    const int h  = blockIdx.y;
    const int b  = blockIdx.z;
    const int kvh = h & (HKV_ - 1);

    const int tid  = threadIdx.x;
    const int w    = tid >> 5;
    const int lane = tid & 31;
    const int g    = lane >> 2;
    const int tg   = lane & 3;
    const int arow_l = (lane & 7) + 8 * ((lane >> 3) & 1);

    const int rloc0 = w * 16 + g;
    const int grow0 = qt * 128 + rloc0;
    const int grow1 = grow0 + 8;

    // ---- load Q once as fp16 A-fragments (pre-scaled by qkv_gemm) ----
    uint32_t qf[8][4];
    {
        const __half* qb = q + ((size_t)(b * Tt_) + qt * 128 + w * 16) * Cc_
                             + h * HDv_;
#pragma unroll
        for (int kc = 0; kc < 8; kc++) {
            const int d0 = kc * 16 + tg * 2;
            qf[kc][0] = *(const uint32_t*)(qb + (size_t)g * Cc_ + d0);
            qf[kc][1] = *(const uint32_t*)(qb + (size_t)(g + 8) * Cc_ + d0);
            qf[kc][2] = *(const uint32_t*)(qb + (size_t)g * Cc_ + d0 + 8);
            qf[kc][3] = *(const uint32_t*)(qb + (size_t)(g + 8) * Cc_ + d0 + 8);
        }
    }

    float of[16][4];
#pragma unroll
    for (int ni = 0; ni < 16; ni++)
#pragma unroll
        for (int r = 0; r < 4; r++) of[ni][r] = 0.f;
    float m0 = -INFINITY, m1 = -INFINITY, l0 = 0.f, l1 = 0.f;

    const __half* kvb0 = kv + (size_t)(b * Tt_) * KVN_ + kvh * HDv_;

    flash_issue_h(sb, 0, kvb0, tid);
    CP_COMMIT();

    for (int kt = 0; kt <= qt; ++kt) {
        const int cur = kt & 1;
        CP_WAIT(0);
        __syncthreads();
        if (kt < qt) {
            flash_issue_h(sb, cur ^ 1, kvb0 + (size_t)(kt + 1) * 128 * KVN_, tid);
            CP_COMMIT();
        }

        const uint32_t vbase = sb + cur * STG_FB + KVB;
        const __half* Kb = (const __half*)(smc + cur * STG_FB);

        const bool diag = (kt == qt);
        const int nimax = diag ? (2 * w + 2) : 16;   // active S n-tiles
        const int kcmax = diag ? (w + 1) : 8;        // active PV k-chunks

        // ---- S = Q K^T ----
        float sf[16][4];
#pragma unroll
        for (int ni = 0; ni < 16; ni++)
#pragma unroll
            for (int r = 0; r < 4; r++) sf[ni][r] = 0.f;

#pragma unroll
        for (int kc = 0; kc < 8; kc++) {
#pragma unroll
            for (int ni = 0; ni < 16; ni++) {
                if (ni < nimax) {
                    uint32_t bfr[2];
                    const __half* krow =
                        Kb + (ni * 8 + g) * LDKH + kc * 16 + tg * 2;
                    bfr[0] = *(const uint32_t*)(krow);
                    bfr[1] = *(const uint32_t*)(krow + 8);
                    mma_f16(sf[ni], qf[kc], bfr);
                }
            }
        }

        // ---- causal mask (diagonal tile only) ----
        if (diag) {
#pragma unroll
            for (int ni = 0; ni < 16; ni++) {
                if (ni >= nimax) {
                    sf[ni][0] = sf[ni][1] = sf[ni][2] = sf[ni][3] = -1e30f;
                } else {
                    const int c0 = kt * 128 + ni * 8 + tg * 2;
                    if (c0 > grow0)     sf[ni][0] = -1e30f;
                    if (c0 + 1 > grow0) sf[ni][1] = -1e30f;
                    if (c0 > grow1)     sf[ni][2] = -1e30f;
                    if (c0 + 1 > grow1) sf[ni][3] = -1e30f;
                }
            }
        }

        // ---- online softmax (rows g, g+8) ----
        float mx0 = -1e30f, mx1 = -1e30f;
#pragma unroll
        for (int ni = 0; ni < 16; ni++) {
            mx0 = fmaxf(mx0, fmaxf(sf[ni][0], sf[ni][1]));
            mx1 = fmaxf(mx1, fmaxf(sf[ni][2], sf[ni][3]));
        }
        mx0 = fmaxf(mx0, __shfl_xor_sync(0xffffffffu, mx0, 1));
        mx0 = fmaxf(mx0, __shfl_xor_sync(0xffffffffu, mx0, 2));
        mx1 = fmaxf(mx1, __shfl_xor_sync(0xffffffffu, mx1, 1));
        mx1 = fmaxf(mx1, __shfl_xor_sync(0xffffffffu, mx1, 2));

        const float nm0 = fmaxf(m0, mx0);
        const float nm1 = fmaxf(m1, mx1);
        float sum0 = 0.f, sum1 = 0.f;
#pragma unroll
        for (int ni = 0; ni < 16; ni++) {
            sf[ni][0] = __expf(sf[ni][0] - nm0);
            sf[ni][1] = __expf(sf[ni][1] - nm0);
            sf[ni][2] = __expf(sf[ni][2] - nm1);
            sf[ni][3] = __expf(sf[ni][3] - nm1);
            sum0 += sf[ni][0] + sf[ni][1];
            sum1 += sf[ni][2] + sf[ni][3];
        }
        sum0 += __shfl_xor_sync(0xffffffffu, sum0, 1);
        sum0 += __shfl_xor_sync(0xffffffffu, sum0, 2);
        sum1 += __shfl_xor_sync(0xffffffffu, sum1, 1);
        sum1 += __shfl_xor_sync(0xffffffffu, sum1, 2);

        const float al0 = __expf(m0 - nm0);
        const float al1 = __expf(m1 - nm1);
        m0 = nm0; m1 = nm1;
        l0 = l0 * al0 + sum0;
        l1 = l1 * al1 + sum1;

        // ---- rescale O ----
        {
            const u64t a0p = pk2(al0, al0);
            const u64t a1p = pk2(al1, al1);
#pragma unroll
            for (int ni = 0; ni < 16; ni++) {
                u64t v01 = pk2(of[ni][0], of[ni][1]);
                u64t v23 = pk2(of[ni][2], of[ni][3]);
                mul2(v01, v01, a0p);
                mul2(v23, v23, a1p);
                const float2 f01 = upk(v01), f23 = upk(v23);
                of[ni][0] = f01.x; of[ni][1] = f01.y;
                of[ni][2] = f23.x; of[ni][3] = f23.y;
            }
        }

        // ---- O += P V : P built in registers from sf (C-frag == A-frag) ----
#pragma unroll
        for (int kc = 0; kc < 8; kc++) {
            if (kc < kcmax) {
                uint32_t pa[4];
                pa[0] = f2h2(sf[2 * kc][0],     sf[2 * kc][1]);
                pa[1] = f2h2(sf[2 * kc][2],     sf[2 * kc][3]);
                pa[2] = f2h2(sf[2 * kc + 1][0], sf[2 * kc + 1][1]);
                pa[3] = f2h2(sf[2 * kc + 1][2], sf[2 * kc + 1][3]);
#pragma unroll
                for (int ni = 0; ni < 16; ni++) {
                    uint32_t vb2[2];
                    ldsm_x2t(vb2, vbase + ((kc * 16 + arow_l) * LDKH + ni * 8) * 2);
                    mma_f16(of[ni], pa, vb2);
                }
            }
        }
    }

    // ---- normalize + store fp16 ----
    const float inv0 = 1.f / l0;
    const float inv1 = 1.f / l1;
    __half* y0 = y + ((size_t)(b * Tt_) + grow0) * Cc_ + h * HDv_;
    __half* y1 = y + ((size_t)(b * Tt_) + grow1) * Cc_ + h * HDv_;
#pragma unroll
    for (int ni = 0; ni < 16; ni++) {
        const int c0 = ni * 8 + tg * 2;
        *(__half2*)(y0 + c0) =
            __floats2half2_rn(of[ni][0] * inv0, of[ni][1] * inv0);
        *(__half2*)(y1 + c0) =
            __floats2half2_rn(of[ni][2] * inv1, of[ni][3] * inv1);
    }
}

// ---------------------------------------------------------------------------
extern "C" void kernel_launch(void* const* d_in, const int* in_sizes, int n_in,
                              void* d_out, int out_size)
{
    const float* x   = (const float*)d_in[0];
    const float* Wkv = (const float*)d_in[1];
    const float* bkv = (const float*)d_in[2];
    const float* Wq  = (const float*)d_in[3];
    const float* bq  = (const float*)d_in[4];
    const float* Wp  = (const float*)d_in[5];
    const float* bp  = (const float*)d_in[6];
    float* out = (float*)d_out;

    __half *qh, *kvh, *yh, *xh, *wqh, *wkvh, *wph;
    cudaGetSymbolAddress((void**)&qh,   g_qh);
    cudaGetSymbolAddress((void**)&kvh,  g_kvh);
    cudaGetSymbolAddress((void**)&yh,   g_yh);
    cudaGetSymbolAddress((void**)&xh,   g_xh);
    cudaGetSymbolAddress((void**)&wqh,  g_wqh);
    cudaGetSymbolAddress((void**)&wkvh, g_wkvh);
    cudaGetSymbolAddress((void**)&wph,  g_wph);

    cudaFuncSetAttribute(qkv_gemm,
                         cudaFuncAttributeMaxDynamicSharedMemorySize,
                         GEMM_SMEM);
    cudaFuncSetAttribute(pgemm_h,
                         cudaFuncAttributeMaxDynamicSharedMemorySize,
                         GEMM_SMEM);
    cudaFuncSetAttribute(flash_h,
                         cudaFuncAttributeMaxDynamicSharedMemorySize,
                         FLASH_SMEM);

    // one fused fp16 conversion of all GEMM inputs
    conv_all<<<18432, 256>>>(x, xh, Wq, wqh, Wkv, wkvh, Wp, wph);

    // fused q + kv projections (q pre-scaled by 1/sqrt(HD))
    qkv_gemm<<<dim3(24, Mm_ / 128), 256, GEMM_SMEM>>>(
        xh, wqh, bq, wkvh, bkv, qh, kvh);
    // attention
    flash_h<<<dim3(Tt_ / 128, Hh_, Bb_), 256, FLASH_SMEM>>>(qh, kvh, yh);
    // out = y @ Wp + bp
    pgemm_h<<<dim3(Cc_ / 128, Mm_ / 128), 256, GEMM_SMEM>>>(yh, wph, bp, out);
}